// round 3
// baseline (speedup 1.0000x reference)
#include <cuda_runtime.h>
#include <cuda_fp16.h>
#include <cstdint>

// loss = mean(relu(||(a-p)W||^2 - ||(a-n)W||^2 + 0.2))   (bias b cancels)

#define ALPHA_C   0.2f
#define BTOT      8192
#define KDIM      2304
#define NDIM      128
#define ROWS_CTA  64
#define KC        32
#define KP        40          // diff row pitch (halves): 80B, conflict-free ldmatrix
#define WP        136         // W row pitch (halves): 272B, conflict-free ldmatrix.trans
#define NCHUNK    (KDIM / KC)       // 72
#define NCTA      (BTOT / ROWS_CTA) // 128

__device__ __half g_Wh[KDIM * NDIM];   // W in native [k][n] layout, fp16
__device__ float  g_partial[NCTA];

// ---------------------------------------------------------------------------
// Coalesced fp32 -> fp16 conversion, layout preserved (no transpose).
__global__ void convW_kernel(const float* __restrict__ W) {
    int gid = blockIdx.x * blockDim.x + threadIdx.x;     // one float4 each
    float4 v = ((const float4*)W)[gid];
    __half2* out = (__half2*)g_Wh;
    out[gid * 2]     = __floats2half2_rn(v.x, v.y);
    out[gid * 2 + 1] = __floats2half2_rn(v.z, v.w);
}

// ---------------------------------------------------------------------------
#define LDSM4(r0, r1, r2, r3, addr)                                          \
    asm volatile("ldmatrix.sync.aligned.m8n8.x4.shared.b16 {%0,%1,%2,%3}, [%4];" \
                 : "=r"(r0), "=r"(r1), "=r"(r2), "=r"(r3) : "r"(addr))

#define LDSM4T(r0, r1, r2, r3, addr)                                         \
    asm volatile("ldmatrix.sync.aligned.m8n8.x4.trans.shared.b16 {%0,%1,%2,%3}, [%4];" \
                 : "=r"(r0), "=r"(r1), "=r"(r2), "=r"(r3) : "r"(addr))

#define MMA16816(c, a0, a1, a2, a3, b0, b1)                                  \
    asm volatile("mma.sync.aligned.m16n8k16.row.col.f32.f16.f16.f32 "        \
                 "{%0,%1,%2,%3}, {%4,%5,%6,%7}, {%8,%9}, {%0,%1,%2,%3};"     \
                 : "+f"(c[0]), "+f"(c[1]), "+f"(c[2]), "+f"(c[3])            \
                 : "r"(a0), "r"(a1), "r"(a2), "r"(a3), "r"(b0), "r"(b1))

__global__ void __launch_bounds__(256, 1)
triplet_main_kernel(const float* __restrict__ A,
                    const float* __restrict__ P,
                    const float* __restrict__ Ng) {
    // static smem: 20480 + 17408 + 1024 + 8 bytes  (< 48 KB, no attribute needed)
    __shared__ __align__(16) __half sdiff[2][128 * KP];   // dp rows 0-63, dn rows 64-127
    __shared__ __align__(16) __half sWt[2][KC * WP];
    __shared__ float sD[128][2];
    __shared__ float sRed[2];

    const int tid  = threadIdx.x;
    const int warp = tid >> 5;
    const int lane = tid & 31;
    const int row0 = blockIdx.x * ROWS_CTA;

    const int mq = warp & 3;       // 32-row slice of the merged 128-row tile
    const int nh = warp >> 2;      // 64-col half

    // staging registers (one chunk ahead)
    float4 ra[2], rp[2], rn[2];
    int4   rw[2];

    float acc[2][8][4];
#pragma unroll
    for (int mt = 0; mt < 2; mt++)
#pragma unroll
        for (int j = 0; j < 8; j++)
#pragma unroll
            for (int c = 0; c < 4; c++) acc[mt][j][c] = 0.f;

    // ldmatrix per-lane address components
    const int a_row  = mq * 32 + (lane & 15);
    const int a_kadd = (lane >> 4) * 8;
    const int b_krow = (lane & 7) + ((lane >> 3) & 1) * 8;
    const int b_ncol = nh * 64 + (lane >> 4) * 8;

    auto loadChunk = [&](int k0) {
#pragma unroll
        for (int it = 0; it < 2; it++) {
            int idx = it * 256 + tid;
            int r = idx >> 3, c4 = idx & 7;            // 64 rows x 8 float4
            long off = (long)(row0 + r) * KDIM + k0 + c4 * 4;
            ra[it] = *(const float4*)(A + off);
            rp[it] = *(const float4*)(P + off);
            rn[it] = *(const float4*)(Ng + off);
        }
#pragma unroll
        for (int it = 0; it < 2; it++) {
            int idx = it * 256 + tid;
            int k = idx >> 4, c = idx & 15;            // 32 k-rows x 16 int4
            rw[it] = *(const int4*)((const __half*)g_Wh + (long)(k0 + k) * NDIM + c * 8);
        }
    };

    auto storeChunk = [&](int buf) {
#pragma unroll
        for (int it = 0; it < 2; it++) {
            int idx = it * 256 + tid;
            int r = idx >> 3, c4 = idx & 7;
            __half2 p01 = __floats2half2_rn(ra[it].x - rp[it].x, ra[it].y - rp[it].y);
            __half2 p23 = __floats2half2_rn(ra[it].z - rp[it].z, ra[it].w - rp[it].w);
            __half2 q01 = __floats2half2_rn(ra[it].x - rn[it].x, ra[it].y - rn[it].y);
            __half2 q23 = __floats2half2_rn(ra[it].z - rn[it].z, ra[it].w - rn[it].w);
            __half2* dp = (__half2*)(&sdiff[buf][r * KP + c4 * 4]);
            dp[0] = p01; dp[1] = p23;
            __half2* dn = (__half2*)(&sdiff[buf][(64 + r) * KP + c4 * 4]);
            dn[0] = q01; dn[1] = q23;
            int k = idx >> 4, c = idx & 15;
            *(int4*)(&sWt[buf][k * WP + c * 8]) = rw[it];
        }
    };

    loadChunk(0);
    storeChunk(0);
    __syncthreads();

    for (int t = 0; t < NCHUNK; t++) {
        if (t + 1 < NCHUNK) loadChunk((t + 1) * KC);   // LDGs in flight under MMA

        const int buf = t & 1;
        const uint32_t a_base = (uint32_t)__cvta_generic_to_shared(&sdiff[buf][0]);
        const uint32_t w_base = (uint32_t)__cvta_generic_to_shared(&sWt[buf][0]);

#pragma unroll
        for (int kk = 0; kk < KC / 16; kk++) {
            const int kb = kk * 16;
            uint32_t A0[4], A1[4];
            LDSM4(A0[0], A0[1], A0[2], A0[3],
                  a_base + (uint32_t)(((a_row) * KP + kb + a_kadd) * 2));
            LDSM4(A1[0], A1[1], A1[2], A1[3],
                  a_base + (uint32_t)(((a_row + 16) * KP + kb + a_kadd) * 2));
#pragma unroll
            for (int nt = 0; nt < 4; nt++) {
                uint32_t B0, B1, B2, B3;
                LDSM4T(B0, B1, B2, B3,
                       w_base + (uint32_t)(((kb + b_krow) * WP + b_ncol + nt * 16) * 2));
                MMA16816(acc[0][2 * nt],     A0[0], A0[1], A0[2], A0[3], B0, B1);
                MMA16816(acc[0][2 * nt + 1], A0[0], A0[1], A0[2], A0[3], B2, B3);
                MMA16816(acc[1][2 * nt],     A1[0], A1[1], A1[2], A1[3], B0, B1);
                MMA16816(acc[1][2 * nt + 1], A1[0], A1[1], A1[2], A1[3], B2, B3);
            }
        }

        if (t + 1 < NCHUNK) storeChunk((t + 1) & 1);   // other buffer; its readers synced at t-1
        __syncthreads();
    }

    // --- epilogue: per-row sum of squares ---
#pragma unroll
    for (int mt = 0; mt < 2; mt++) {
        float slo = 0.f, shi = 0.f;
#pragma unroll
        for (int j = 0; j < 8; j++) {
            slo += acc[mt][j][0] * acc[mt][j][0] + acc[mt][j][1] * acc[mt][j][1];
            shi += acc[mt][j][2] * acc[mt][j][2] + acc[mt][j][3] * acc[mt][j][3];
        }
        slo += __shfl_xor_sync(0xffffffffu, slo, 1);
        slo += __shfl_xor_sync(0xffffffffu, slo, 2);
        shi += __shfl_xor_sync(0xffffffffu, shi, 1);
        shi += __shfl_xor_sync(0xffffffffu, shi, 2);
        if ((lane & 3) == 0) {
            int r = mq * 32 + mt * 16 + (lane >> 2);
            sD[r][nh]     = slo;
            sD[r + 8][nh] = shi;
        }
    }
    __syncthreads();

    if (tid < 64) {
        float dp = sD[tid][0] + sD[tid][1];
        float dn = sD[tid + 64][0] + sD[tid + 64][1];
        float loss = dp - dn + ALPHA_C;
        loss = loss > 0.f ? loss : 0.f;
#pragma unroll
        for (int o = 16; o > 0; o >>= 1)
            loss += __shfl_xor_sync(0xffffffffu, loss, o);
        if (lane == 0) sRed[warp] = loss;
    }
    __syncthreads();
    if (tid == 0) g_partial[blockIdx.x] = sRed[0] + sRed[1];
}

// ---------------------------------------------------------------------------
__global__ void reduce_kernel(float* __restrict__ out) {
    __shared__ float sm[4];
    int tid = threadIdx.x;               // 128
    float s = g_partial[tid];
#pragma unroll
    for (int o = 16; o > 0; o >>= 1) s += __shfl_xor_sync(0xffffffffu, s, o);
    if ((tid & 31) == 0) sm[tid >> 5] = s;
    __syncthreads();
    if (tid == 0)
        out[0] = (sm[0] + sm[1] + sm[2] + sm[3]) * (1.0f / (float)BTOT);
}

// ---------------------------------------------------------------------------
extern "C" void kernel_launch(void* const* d_in, const int* in_sizes, int n_in,
                              void* d_out, int out_size) {
    const float* A  = (const float*)d_in[0];  // batch_anchor
    const float* P  = (const float*)d_in[1];  // batch_pos
    const float* Ng = (const float*)d_in[2];  // batch_neg
    const float* W  = (const float*)d_in[3];  // W (b cancels)

    convW_kernel<<<(KDIM * NDIM / 4) / 256, 256>>>(W);
    triplet_main_kernel<<<NCTA, 256>>>(A, P, Ng);
    reduce_kernel<<<1, 128>>>((float*)d_out);
}

// round 4
// speedup vs baseline: 1.4398x; 1.4398x over previous
#include <cuda_runtime.h>
#include <cuda_fp16.h>
#include <cstdint>

// loss = mean(relu(||(a-p)W||^2 - ||(a-n)W||^2 + 0.2))   (bias b cancels)

#define ALPHA_C   0.2f
#define BTOT      8192
#define KDIM      2304
#define NDIM      128
#define ROWS_CTA  64
#define KC        64
#define KP        72          // diff row pitch (halves): conflict-free ldmatrix
#define WP        136         // W row pitch (halves): conflict-free ldmatrix.trans
#define NCHUNK    (KDIM / KC)       // 36
#define NCTA      (BTOT / ROWS_CTA) // 128

__device__ float g_partial[NCTA];

// ---------------------------------------------------------------------------
#define LDSM4(r0, r1, r2, r3, addr)                                          \
    asm volatile("ldmatrix.sync.aligned.m8n8.x4.shared.b16 {%0,%1,%2,%3}, [%4];" \
                 : "=r"(r0), "=r"(r1), "=r"(r2), "=r"(r3) : "r"(addr))

#define LDSM4T(r0, r1, r2, r3, addr)                                         \
    asm volatile("ldmatrix.sync.aligned.m8n8.x4.trans.shared.b16 {%0,%1,%2,%3}, [%4];" \
                 : "=r"(r0), "=r"(r1), "=r"(r2), "=r"(r3) : "r"(addr))

#define MMA16816(c, a0, a1, a2, a3, b0, b1)                                  \
    asm volatile("mma.sync.aligned.m16n8k16.row.col.f32.f16.f16.f32 "        \
                 "{%0,%1,%2,%3}, {%4,%5,%6,%7}, {%8,%9}, {%0,%1,%2,%3};"     \
                 : "+f"(c[0]), "+f"(c[1]), "+f"(c[2]), "+f"(c[3])            \
                 : "r"(a0), "r"(a1), "r"(a2), "r"(a3), "r"(b0), "r"(b1))

__global__ void __launch_bounds__(256, 1)
triplet_main_kernel(const float* __restrict__ A,
                    const float* __restrict__ P,
                    const float* __restrict__ Ng,
                    const float* __restrict__ W) {
    // static smem: 18432 + 17408 + 1024 + 8 bytes (< 48 KB)
    __shared__ __align__(16) __half sdiff[128 * KP];  // dp rows 0-63, dn rows 64-127
    __shared__ __align__(16) __half sWt[KC * WP];
    __shared__ float sD[128][2];
    __shared__ float sRed[2];

    const int tid  = threadIdx.x;
    const int warp = tid >> 5;
    const int lane = tid & 31;
    const int row0 = blockIdx.x * ROWS_CTA;

    const int mq = warp & 3;       // 32-row slice of the merged 128-row tile
    const int nh = warp >> 2;      // 64-col half

    // staging registers (one chunk ahead)
    float4 ra[4], rp[4], rn[4];    // 64 rows x 64 floats / 256 thr = 4 float4 each
    float4 rw[8];                  // 64 k-rows x 128 floats / 256 thr = 8 float4 each

    float acc[2][8][4];
#pragma unroll
    for (int mt = 0; mt < 2; mt++)
#pragma unroll
        for (int j = 0; j < 8; j++)
#pragma unroll
            for (int c = 0; c < 4; c++) acc[mt][j][c] = 0.f;

    // ldmatrix per-lane address components
    const int a_row  = mq * 32 + (lane & 15);
    const int a_kadd = (lane >> 4) * 8;
    const int b_krow = (lane & 7) + ((lane >> 3) & 1) * 8;
    const int b_ncol = nh * 64 + (lane >> 4) * 8;

    auto loadChunk = [&](int k0) {
#pragma unroll
        for (int it = 0; it < 4; it++) {
            int idx = it * 256 + tid;
            int r = idx >> 4, c4 = idx & 15;           // 16 float4 per 64-float row
            long off = (long)(row0 + r) * KDIM + k0 + c4 * 4;
            ra[it] = *(const float4*)(A + off);
            rp[it] = *(const float4*)(P + off);
            rn[it] = *(const float4*)(Ng + off);
        }
#pragma unroll
        for (int it = 0; it < 8; it++) {
            int idx = it * 256 + tid;
            int k = idx >> 5, c = idx & 31;            // 32 float4 per 128-float row
            rw[it] = *(const float4*)(W + (long)(k0 + k) * NDIM + c * 4);
        }
    };

    auto storeChunk = [&]() {
#pragma unroll
        for (int it = 0; it < 4; it++) {
            int idx = it * 256 + tid;
            int r = idx >> 4, c4 = idx & 15;
            __half2 p01 = __floats2half2_rn(ra[it].x - rp[it].x, ra[it].y - rp[it].y);
            __half2 p23 = __floats2half2_rn(ra[it].z - rp[it].z, ra[it].w - rp[it].w);
            __half2 q01 = __floats2half2_rn(ra[it].x - rn[it].x, ra[it].y - rn[it].y);
            __half2 q23 = __floats2half2_rn(ra[it].z - rn[it].z, ra[it].w - rn[it].w);
            __half2* dp = (__half2*)(&sdiff[r * KP + c4 * 4]);
            dp[0] = p01; dp[1] = p23;
            __half2* dn = (__half2*)(&sdiff[(64 + r) * KP + c4 * 4]);
            dn[0] = q01; dn[1] = q23;
        }
#pragma unroll
        for (int it = 0; it < 8; it++) {
            int idx = it * 256 + tid;
            int k = idx >> 5, c = idx & 31;
            __half2* dst = (__half2*)(&sWt[k * WP + c * 4]);
            dst[0] = __floats2half2_rn(rw[it].x, rw[it].y);
            dst[1] = __floats2half2_rn(rw[it].z, rw[it].w);
        }
    };

    const uint32_t a_base = (uint32_t)__cvta_generic_to_shared(sdiff);
    const uint32_t w_base = (uint32_t)__cvta_generic_to_shared(sWt);

    loadChunk(0);

    for (int t = 0; t < NCHUNK; t++) {
        __syncthreads();                              // MMA of t-1 done with smem
        storeChunk();                                 // stage chunk t into smem
        __syncthreads();                              // visible to all warps
        if (t + 1 < NCHUNK) loadChunk((t + 1) * KC);  // LDGs in flight under MMA

#pragma unroll
        for (int kk = 0; kk < KC / 16; kk++) {
            const int kb = kk * 16;
            uint32_t A0[4], A1[4];
            LDSM4(A0[0], A0[1], A0[2], A0[3],
                  a_base + (uint32_t)(((a_row) * KP + kb + a_kadd) * 2));
            LDSM4(A1[0], A1[1], A1[2], A1[3],
                  a_base + (uint32_t)(((a_row + 16) * KP + kb + a_kadd) * 2));
#pragma unroll
            for (int nt = 0; nt < 4; nt++) {
                uint32_t B0, B1, B2, B3;
                LDSM4T(B0, B1, B2, B3,
                       w_base + (uint32_t)(((kb + b_krow) * WP + b_ncol + nt * 16) * 2));
                MMA16816(acc[0][2 * nt],     A0[0], A0[1], A0[2], A0[3], B0, B1);
                MMA16816(acc[0][2 * nt + 1], A0[0], A0[1], A0[2], A0[3], B2, B3);
                MMA16816(acc[1][2 * nt],     A1[0], A1[1], A1[2], A1[3], B0, B1);
                MMA16816(acc[1][2 * nt + 1], A1[0], A1[1], A1[2], A1[3], B2, B3);
            }
        }
    }

    // --- epilogue: per-row sum of squares ---
#pragma unroll
    for (int mt = 0; mt < 2; mt++) {
        float slo = 0.f, shi = 0.f;
#pragma unroll
        for (int j = 0; j < 8; j++) {
            slo += acc[mt][j][0] * acc[mt][j][0] + acc[mt][j][1] * acc[mt][j][1];
            shi += acc[mt][j][2] * acc[mt][j][2] + acc[mt][j][3] * acc[mt][j][3];
        }
        slo += __shfl_xor_sync(0xffffffffu, slo, 1);
        slo += __shfl_xor_sync(0xffffffffu, slo, 2);
        shi += __shfl_xor_sync(0xffffffffu, shi, 1);
        shi += __shfl_xor_sync(0xffffffffu, shi, 2);
        if ((lane & 3) == 0) {
            int r = mq * 32 + mt * 16 + (lane >> 2);
            sD[r][nh]     = slo;
            sD[r + 8][nh] = shi;
        }
    }
    __syncthreads();

    if (tid < 64) {
        float dp = sD[tid][0] + sD[tid][1];
        float dn = sD[tid + 64][0] + sD[tid + 64][1];
        float loss = dp - dn + ALPHA_C;
        loss = loss > 0.f ? loss : 0.f;
#pragma unroll
        for (int o = 16; o > 0; o >>= 1)
            loss += __shfl_xor_sync(0xffffffffu, loss, o);
        if (lane == 0) sRed[warp] = loss;
    }
    __syncthreads();
    if (tid == 0) g_partial[blockIdx.x] = sRed[0] + sRed[1];
}

// ---------------------------------------------------------------------------
__global__ void reduce_kernel(float* __restrict__ out) {
    __shared__ float sm[4];
    int tid = threadIdx.x;               // 128
    float s = g_partial[tid];
#pragma unroll
    for (int o = 16; o > 0; o >>= 1) s += __shfl_xor_sync(0xffffffffu, s, o);
    if ((tid & 31) == 0) sm[tid >> 5] = s;
    __syncthreads();
    if (tid == 0)
        out[0] = (sm[0] + sm[1] + sm[2] + sm[3]) * (1.0f / (float)BTOT);
}

// ---------------------------------------------------------------------------
extern "C" void kernel_launch(void* const* d_in, const int* in_sizes, int n_in,
                              void* d_out, int out_size) {
    const float* A  = (const float*)d_in[0];  // batch_anchor
    const float* P  = (const float*)d_in[1];  // batch_pos
    const float* Ng = (const float*)d_in[2];  // batch_neg
    const float* W  = (const float*)d_in[3];  // W (b cancels)

    triplet_main_kernel<<<NCTA, 256>>>(A, P, Ng, W);
    reduce_kernel<<<1, 128>>>((float*)d_out);
}

// round 5
// speedup vs baseline: 1.4423x; 1.0017x over previous
#include <cuda_runtime.h>
#include <cuda_fp16.h>
#include <cstdint>

// loss = mean(relu(||(a-p)W||^2 - ||(a-n)W||^2 + 0.2))   (bias b cancels)

#define ALPHA_C   0.2f
#define BTOT      8192
#define KDIM      2304
#define NDIM      128
#define ROWS_CTA  64
#define KC        64
#define KP        72          // diff row pitch (halves): conflict-free ldmatrix
#define WP        136         // W row pitch (halves): conflict-free ldmatrix.trans
#define NCHUNK    (KDIM / KC)       // 36
#define NCTA      (BTOT / ROWS_CTA) // 128

__device__ float    g_partial[NCTA];
__device__ unsigned g_ticket = 0;

static __device__ __forceinline__ uint32_t h2u(__half2 h) {
    return *reinterpret_cast<uint32_t*>(&h);
}

// ---------------------------------------------------------------------------
#define LDSM4(r0, r1, r2, r3, addr)                                          \
    asm volatile("ldmatrix.sync.aligned.m8n8.x4.shared.b16 {%0,%1,%2,%3}, [%4];" \
                 : "=r"(r0), "=r"(r1), "=r"(r2), "=r"(r3) : "r"(addr))

#define LDSM4T(r0, r1, r2, r3, addr)                                         \
    asm volatile("ldmatrix.sync.aligned.m8n8.x4.trans.shared.b16 {%0,%1,%2,%3}, [%4];" \
                 : "=r"(r0), "=r"(r1), "=r"(r2), "=r"(r3) : "r"(addr))

#define MMA16816(c, a0, a1, a2, a3, b0, b1)                                  \
    asm volatile("mma.sync.aligned.m16n8k16.row.col.f32.f16.f16.f32 "        \
                 "{%0,%1,%2,%3}, {%4,%5,%6,%7}, {%8,%9}, {%0,%1,%2,%3};"     \
                 : "+f"(c[0]), "+f"(c[1]), "+f"(c[2]), "+f"(c[3])            \
                 : "r"(a0), "r"(a1), "r"(a2), "r"(a3), "r"(b0), "r"(b1))

__global__ void __launch_bounds__(256, 1)
triplet_main_kernel(const float* __restrict__ A,
                    const float* __restrict__ P,
                    const float* __restrict__ Ng,
                    const float* __restrict__ W,
                    float* __restrict__ out) {
    // static smem: 18432 + 17408 + 1024 + ~ bytes (< 48 KB)
    __shared__ __align__(16) __half sdiff[128 * KP];  // dp rows 0-63, dn rows 64-127
    __shared__ __align__(16) __half sWt[KC * WP];
    __shared__ float sD[128][2];
    __shared__ float sRed[4];
    __shared__ int   sIsLast;

    const int tid  = threadIdx.x;
    const int warp = tid >> 5;
    const int lane = tid & 31;
    const int row0 = blockIdx.x * ROWS_CTA;

    const int mq = warp & 3;       // 32-row slice of the merged 128-row tile
    const int nh = warp >> 2;      // 64-col half

    // staging registers (one chunk ahead)
    float4 ra[4], rp[4], rn[4];    // 64 rows x 64 floats / 256 thr = 4 float4 each
    float4 rw[8];                  // 64 k-rows x 128 floats / 256 thr = 8 float4 each

    float acc[2][8][4];
#pragma unroll
    for (int mt = 0; mt < 2; mt++)
#pragma unroll
        for (int j = 0; j < 8; j++)
#pragma unroll
            for (int c = 0; c < 4; c++) acc[mt][j][c] = 0.f;

    // ldmatrix per-lane address components
    const int a_row  = mq * 32 + (lane & 15);
    const int a_kadd = (lane >> 4) * 8;
    const int b_krow = (lane & 7) + ((lane >> 3) & 1) * 8;
    const int b_ncol = nh * 64 + (lane >> 4) * 8;

    auto loadChunk = [&](int k0) {
#pragma unroll
        for (int it = 0; it < 4; it++) {
            int idx = it * 256 + tid;
            int r = idx >> 4, c4 = idx & 15;           // 16 float4 per 64-float row
            long off = (long)(row0 + r) * KDIM + k0 + c4 * 4;
            ra[it] = *(const float4*)(A + off);
            rp[it] = *(const float4*)(P + off);
            rn[it] = *(const float4*)(Ng + off);
        }
#pragma unroll
        for (int it = 0; it < 8; it++) {
            int idx = it * 256 + tid;
            int k = idx >> 5, c = idx & 31;            // 32 float4 per 128-float row
            rw[it] = *(const float4*)(W + (long)(k0 + k) * NDIM + c * 4);
        }
    };

    auto storeChunk = [&]() {
#pragma unroll
        for (int it = 0; it < 4; it++) {
            int idx = it * 256 + tid;
            int r = idx >> 4, c4 = idx & 15;
            __half2 p01 = __floats2half2_rn(ra[it].x - rp[it].x, ra[it].y - rp[it].y);
            __half2 p23 = __floats2half2_rn(ra[it].z - rp[it].z, ra[it].w - rp[it].w);
            __half2 q01 = __floats2half2_rn(ra[it].x - rn[it].x, ra[it].y - rn[it].y);
            __half2 q23 = __floats2half2_rn(ra[it].z - rn[it].z, ra[it].w - rn[it].w);
            uint2 vp = make_uint2(h2u(p01), h2u(p23));
            uint2 vq = make_uint2(h2u(q01), h2u(q23));
            *(uint2*)(&sdiff[r * KP + c4 * 4])        = vp;   // STS.64
            *(uint2*)(&sdiff[(64 + r) * KP + c4 * 4]) = vq;   // STS.64
        }
#pragma unroll
        for (int it = 0; it < 8; it++) {
            int idx = it * 256 + tid;
            int k = idx >> 5, c = idx & 31;
            uint2 vw = make_uint2(h2u(__floats2half2_rn(rw[it].x, rw[it].y)),
                                  h2u(__floats2half2_rn(rw[it].z, rw[it].w)));
            *(uint2*)(&sWt[k * WP + c * 4]) = vw;             // STS.64
        }
    };

    const uint32_t a_base = (uint32_t)__cvta_generic_to_shared(sdiff);
    const uint32_t w_base = (uint32_t)__cvta_generic_to_shared(sWt);

    loadChunk(0);

    for (int t = 0; t < NCHUNK; t++) {
        __syncthreads();                              // MMA of t-1 done with smem
        storeChunk();                                 // stage chunk t into smem
        __syncthreads();                              // visible to all warps
        if (t + 1 < NCHUNK) loadChunk((t + 1) * KC);  // LDGs in flight under MMA

#pragma unroll
        for (int kk = 0; kk < KC / 16; kk++) {
            const int kb = kk * 16;
            uint32_t A0[4], A1[4];
            LDSM4(A0[0], A0[1], A0[2], A0[3],
                  a_base + (uint32_t)(((a_row) * KP + kb + a_kadd) * 2));
            LDSM4(A1[0], A1[1], A1[2], A1[3],
                  a_base + (uint32_t)(((a_row + 16) * KP + kb + a_kadd) * 2));
#pragma unroll
            for (int nt = 0; nt < 4; nt++) {
                uint32_t B0, B1, B2, B3;
                LDSM4T(B0, B1, B2, B3,
                       w_base + (uint32_t)(((kb + b_krow) * WP + b_ncol + nt * 16) * 2));
                MMA16816(acc[0][2 * nt],     A0[0], A0[1], A0[2], A0[3], B0, B1);
                MMA16816(acc[0][2 * nt + 1], A0[0], A0[1], A0[2], A0[3], B2, B3);
                MMA16816(acc[1][2 * nt],     A1[0], A1[1], A1[2], A1[3], B0, B1);
                MMA16816(acc[1][2 * nt + 1], A1[0], A1[1], A1[2], A1[3], B2, B3);
            }
        }
    }

    // --- epilogue: per-row sum of squares ---
#pragma unroll
    for (int mt = 0; mt < 2; mt++) {
        float slo = 0.f, shi = 0.f;
#pragma unroll
        for (int j = 0; j < 8; j++) {
            slo += acc[mt][j][0] * acc[mt][j][0] + acc[mt][j][1] * acc[mt][j][1];
            shi += acc[mt][j][2] * acc[mt][j][2] + acc[mt][j][3] * acc[mt][j][3];
        }
        slo += __shfl_xor_sync(0xffffffffu, slo, 1);
        slo += __shfl_xor_sync(0xffffffffu, slo, 2);
        shi += __shfl_xor_sync(0xffffffffu, shi, 1);
        shi += __shfl_xor_sync(0xffffffffu, shi, 2);
        if ((lane & 3) == 0) {
            int r = mq * 32 + mt * 16 + (lane >> 2);
            sD[r][nh]     = slo;
            sD[r + 8][nh] = shi;
        }
    }
    __syncthreads();

    if (tid < 64) {
        float dp = sD[tid][0] + sD[tid][1];
        float dn = sD[tid + 64][0] + sD[tid + 64][1];
        float loss = dp - dn + ALPHA_C;
        loss = loss > 0.f ? loss : 0.f;
#pragma unroll
        for (int o = 16; o > 0; o >>= 1)
            loss += __shfl_xor_sync(0xffffffffu, loss, o);
        if (lane == 0) sRed[warp] = loss;
    }
    __syncthreads();

    // --- publish partial; last CTA reduces all partials (threadFenceReduction) ---
    if (tid == 0) {
        g_partial[blockIdx.x] = sRed[0] + sRed[1];
        __threadfence();
        unsigned ticket = atomicAdd(&g_ticket, 1u);
        sIsLast = (ticket == NCTA - 1);
    }
    __syncthreads();

    if (sIsLast) {
        if (tid < NCTA) {
            float s = g_partial[tid];
#pragma unroll
            for (int o = 16; o > 0; o >>= 1)
                s += __shfl_xor_sync(0xffffffffu, s, o);
            if (lane == 0) sRed[warp] = s;
        }
        __syncthreads();
        if (tid == 0) {
            out[0] = (sRed[0] + sRed[1] + sRed[2] + sRed[3]) * (1.0f / (float)BTOT);
            g_ticket = 0;   // reset for next (graph-replayed) launch: deterministic
        }
    }
}

// ---------------------------------------------------------------------------
extern "C" void kernel_launch(void* const* d_in, const int* in_sizes, int n_in,
                              void* d_out, int out_size) {
    const float* A  = (const float*)d_in[0];  // batch_anchor
    const float* P  = (const float*)d_in[1];  // batch_pos
    const float* Ng = (const float*)d_in[2];  // batch_neg
    const float* W  = (const float*)d_in[3];  // W (b cancels)

    triplet_main_kernel<<<NCTA, 256>>>(A, P, Ng, W, (float*)d_out);
}